// round 9
// baseline (speedup 1.0000x reference)
#include <cuda_runtime.h>
#include <cuda_bf16.h>
#include <cstdint>

// ============================================================
// W8A8 linear: out[M,N] = xs * (Xq[M,K] @ Wq[N,K]^T) * wsc[n] + bias[n]
//   M = 8192, N = 4096, K = 4096
// Base-sm_103 (compute_103 virtual arch; no tcgen05).
// Round 9: R7 base (BK=128, 2-stage, persistent; stagger reverted).
// cp.async issuance for the next kit is SPREAD ACROSS the j-loop
// (3 chunks after each of the 8 j-steps) so the per-kit LDGSTS
// issue burst (24 ops x rt8 ~ 192 cyc/warp) no longer starves the
// tensor pipe at kit start.
// ============================================================

#define MM 8192
#define NN 4096
#define KK 4096

#define BM 128
#define BN 256
#define BK 128                // bf16 elements; 256 bytes per row
#define STAGES 2
#define KITERS (KK / BK)      // 32
#define NTHREADS 256          // 8 warps
#define TILES_X (NN / BN)     // 16
#define NTILES ((MM / BM) * (NN / BN))   // 1024

// ---- device scratch: quantized bf16 operands ----
__device__ __align__(128) __nv_bfloat16 g_xq[(size_t)MM * KK];
__device__ __align__(128) __nv_bfloat16 g_wq[(size_t)NN * KK];

// ============================================================
// PTX helpers (base-arch only)
// ============================================================
__device__ __forceinline__ uint32_t smem_to_u32(const void* p) {
    uint32_t a;
    asm("{ .reg .u64 t; cvta.to.shared.u64 t, %1; cvt.u32.u64 %0, t; }"
        : "=r"(a) : "l"(p));
    return a;
}

__device__ __forceinline__ void cp_async16(uint32_t dst, const void* src) {
    asm volatile("cp.async.cg.shared.global [%0], [%1], 16;"
                 :: "r"(dst), "l"(src) : "memory");
}
#define CP_COMMIT() asm volatile("cp.async.commit_group;" ::: "memory")
#define CP_WAIT(n)  asm volatile("cp.async.wait_group %0;" :: "n"(n) : "memory")

#define LDMATRIX_X4(r, addr) \
    asm volatile("ldmatrix.sync.aligned.m8n8.x4.shared.b16 {%0,%1,%2,%3}, [%4];" \
                 : "=r"((r)[0]), "=r"((r)[1]), "=r"((r)[2]), "=r"((r)[3]) \
                 : "r"(addr))

// D(16x8 f32) += A(16x16 bf16, row-major) * B(16x8 bf16, col operand)
__device__ __forceinline__ void mma_bf16(float* d, const uint32_t* a,
                                         uint32_t b0, uint32_t b1) {
    asm volatile(
        "mma.sync.aligned.m16n8k16.row.col.f32.bf16.bf16.f32 "
        "{%0,%1,%2,%3}, {%4,%5,%6,%7}, {%8,%9}, {%0,%1,%2,%3};"
        : "+f"(d[0]), "+f"(d[1]), "+f"(d[2]), "+f"(d[3])
        : "r"(a[0]), "r"(a[1]), "r"(a[2]), "r"(a[3]),
          "r"(b0), "r"(b1));
}

// ============================================================
// Fused quantization pre-pass (x -> g_xq scaled; w -> g_wq passthrough)
// ============================================================
__device__ __forceinline__ uint2 quant4_bf16(float4 v, float inv) {
    float a = fminf(127.f, fmaxf(-128.f, rintf(v.x * inv)));
    float b = fminf(127.f, fmaxf(-128.f, rintf(v.y * inv)));
    float c = fminf(127.f, fmaxf(-128.f, rintf(v.z * inv)));
    float d = fminf(127.f, fmaxf(-128.f, rintf(v.w * inv)));
    __nv_bfloat162 lo = __floats2bfloat162_rn(a, b);
    __nv_bfloat162 hi = __floats2bfloat162_rn(c, d);
    uint2 p;
    p.x = *reinterpret_cast<uint32_t*>(&lo);
    p.y = *reinterpret_cast<uint32_t*>(&hi);
    return p;
}

__global__ void quantize_kernel(const float4* __restrict__ x4,
                                const float4* __restrict__ w4,
                                const float* __restrict__ xs_ptr,
                                int n4x, int n4tot) {
    int i = blockIdx.x * blockDim.x + threadIdx.x;
    if (i >= n4tot) return;
    if (i < n4x) {
        float inv = 1.0f / __ldg(xs_ptr);
        reinterpret_cast<uint2*>(g_xq)[i] = quant4_bf16(x4[i], inv);
    } else {
        int j = i - n4x;
        float4 v = w4[j];   // already integer-valued
        __nv_bfloat162 lo = __floats2bfloat162_rn(v.x, v.y);
        __nv_bfloat162 hi = __floats2bfloat162_rn(v.z, v.w);
        uint2 p;
        p.x = *reinterpret_cast<uint32_t*>(&lo);
        p.y = *reinterpret_cast<uint32_t*>(&hi);
        reinterpret_cast<uint2*>(g_wq)[j] = p;
    }
}

// ============================================================
// GEMM kernel: persistent CTAs, 2-stage double buffer, BK=128.
//   256 threads = 8 warps, warp grid 2(m) x 4(n), warp tile 64x64.
//   Rows are 256B (two 128B halves); swizzle within each half:
//   off = row*256 + (chunk&8)*16 + (((chunk&7) ^ (row&7)) << 4)
//   -> ldmatrix conflict-free.
// Per kit: wait(0) -> barrier -> 8 j-steps, each followed by 3 of the
// 24 cp.async chunks for the next kit -> commit.
// ============================================================
#define SOFF_SC   0
#define SOFF_BI   1024
#define SOFF_ST   2048
#define ROWB      256                          // bytes per smem row
#define STAGE_BYTES ((BM + BN) * ROWB)         // 98304
#define ASTAGE(s) (SOFF_ST + (s) * STAGE_BYTES)
#define BSTAGE(s) (ASTAGE(s) + BM * ROWB)
#define SMEM_TOTAL (SOFF_ST + STAGES * STAGE_BYTES)   // 198656
#define NCHUNK ((BM + BN) * 16 / NTHREADS)     // 24 per thread per kit

__device__ __forceinline__ uint32_t swz(int row, int chunk) {
    return (uint32_t)(row * ROWB + ((chunk & 8) << 4) +
                      (((chunk & 7) ^ (row & 7)) << 4));
}

__global__ void __launch_bounds__(NTHREADS, 1)
w8a8_gemm_kernel(float* __restrict__ out,
                 const float* __restrict__ wsc,
                 const float* __restrict__ bias,
                 const float* __restrict__ xs_ptr) {
    extern __shared__ char smem[];
    uint32_t sb = smem_to_u32(smem);
    int tid  = threadIdx.x;
    int wid  = tid >> 5;
    int lane = tid & 31;
    int warp_m = wid & 1;     // m offset warp_m*64
    int warp_n = wid >> 1;    // n offset warp_n*64
    int G = gridDim.x;

    // ---- load cursor: continuous across this CTA's tile list ----
    int ltile = blockIdx.x;
    int lkit  = 0;
    int ls    = 0;

    // ---- stage sc/bias for first tile ----
    {
        int n0 = (blockIdx.x % TILES_X) * BN;
        for (int c = tid; c < BN; c += NTHREADS) {
            reinterpret_cast<float*>(smem + SOFF_SC)[c] = wsc[n0 + c];
            reinterpret_cast<float*>(smem + SOFF_BI)[c] = bias[n0 + c];
        }
    }

    // prologue: load kit 0 into stage 0 (burst is fine here, once)
    {
        int lm0 = (ltile / TILES_X) * BM;
        int ln0 = (ltile % TILES_X) * BN;
        const __nv_bfloat16* Ab = g_xq + (size_t)lm0 * KK;
        const __nv_bfloat16* Bb = g_wq + (size_t)ln0 * KK;
        #pragma unroll
        for (int i = 0; i < NCHUNK; i++) {
            int idx = tid + i * NTHREADS;
            int row = idx >> 4;
            int c = idx & 15;
            if (row < BM)
                cp_async16(sb + ASTAGE(ls) + swz(row, c),
                           Ab + (size_t)row * KK + c * 8);
            else
                cp_async16(sb + BSTAGE(ls) + swz(row - BM, c),
                           Bb + (size_t)(row - BM) * KK + c * 8);
        }
        ls ^= 1;
        if (++lkit == KITERS) { lkit = 0; ltile += G; }
        CP_COMMIT();
    }

    float xs = __ldg(xs_ptr);

    // ldmatrix lane address components (validated in rounds 3-8)
    int arow  = lane & 15;                        // A rows within m16
    int ahalf = lane >> 4;                        // A 16B half of k16 (32B)
    int brow  = (lane & 7) + ((lane & 16) >> 1);  // B n-rows (two n8 tiles)
    int bhalf = (lane >> 3) & 1;                  // B 16B half of k16

    int cs = 0;   // compute stage

    for (int mytile = blockIdx.x; mytile < NTILES; mytile += G) {
        int m0 = (mytile / TILES_X) * BM;
        int n0 = (mytile % TILES_X) * BN;

        float acc[4][8][4] = {};   // [m16 tile][n8 tile][frag]

        for (int kit = 0; kit < KITERS; kit++) {
            CP_WAIT(0);           // this kit's data (had a full slab to land)
            __syncthreads();      // everyone done reading the other stage

            // snapshot this kit's load work (next stage), advance cursor
            bool doload = (ltile < NTILES);
            const __nv_bfloat16* Ab = nullptr;
            const __nv_bfloat16* Bb = nullptr;
            uint32_t Adst = sb + ASTAGE(ls);
            uint32_t Bdst = sb + BSTAGE(ls);
            if (doload) {
                int lm0 = (ltile / TILES_X) * BM;
                int ln0 = (ltile % TILES_X) * BN;
                int k0 = lkit * BK;
                Ab = g_xq + (size_t)lm0 * KK + k0;
                Bb = g_wq + (size_t)ln0 * KK + k0;
                ls ^= 1;
                if (++lkit == KITERS) { lkit = 0; ltile += G; }
            }

            uint32_t As = sb + ASTAGE(cs);
            uint32_t Bs = sb + BSTAGE(cs);
            cs ^= 1;

            #pragma unroll
            for (int j = 0; j < BK / 16; j++) {      // 8 k16 steps
                uint32_t a[4][4];
                #pragma unroll
                for (int t = 0; t < 4; t++) {
                    int row = warp_m * 64 + t * 16 + arow;
                    LDMATRIX_X4(a[t], As + swz(row, j * 2 + ahalf));
                }
                uint32_t b[4][4];
                #pragma unroll
                for (int p = 0; p < 4; p++) {
                    int row = warp_n * 64 + p * 16 + brow;
                    LDMATRIX_X4(b[p], Bs + swz(row, j * 2 + bhalf));
                }
                #pragma unroll
                for (int t = 0; t < 4; t++) {
                    #pragma unroll
                    for (int p = 0; p < 4; p++) {
                        mma_bf16(acc[t][2 * p],     a[t], b[p][0], b[p][1]);
                        mma_bf16(acc[t][2 * p + 1], a[t], b[p][2], b[p][3]);
                    }
                }
                // spread next kit's loads: 3 chunks per j-step (8*3 = 24)
                if (doload) {
                    #pragma unroll
                    for (int u = 0; u < NCHUNK / 8; u++) {
                        int idx = tid + (j * (NCHUNK / 8) + u) * NTHREADS;
                        int row = idx >> 4;
                        int c = idx & 15;
                        if (row < BM)
                            cp_async16(Adst + swz(row, c),
                                       Ab + (size_t)row * KK + c * 8);
                        else
                            cp_async16(Bdst + swz(row - BM, c),
                                       Bb + (size_t)(row - BM) * KK + c * 8);
                    }
                }
            }
            CP_COMMIT();
        }

        // -------- epilogue: out = acc * xs * sc[n] + bias[n] --------
        // (next tile's kit-0 cp.async already in flight underneath)
        const float* sc = reinterpret_cast<const float*>(smem + SOFF_SC);
        const float* bi = reinterpret_cast<const float*>(smem + SOFF_BI);
        int rbase = m0 + warp_m * 64 + (lane >> 2);
        #pragma unroll
        for (int t = 0; t < 4; t++) {
            #pragma unroll
            for (int q = 0; q < 8; q++) {
                int col = warp_n * 64 + q * 8 + (lane & 3) * 2;
                float s0 = xs * sc[col],     s1 = xs * sc[col + 1];
                float b0 = bi[col],          b1 = bi[col + 1];
                int row = rbase + t * 16;
                float2 v0, v1;
                v0.x = acc[t][q][0] * s0 + b0;
                v0.y = acc[t][q][1] * s1 + b1;
                v1.x = acc[t][q][2] * s0 + b0;
                v1.y = acc[t][q][3] * s1 + b1;
                *reinterpret_cast<float2*>(out + (size_t)row * NN + n0 + col) = v0;
                *reinterpret_cast<float2*>(out + (size_t)(row + 8) * NN + n0 + col) = v1;
            }
        }

        // restage sc/bias for next tile (separate smem region from stages)
        int nt = mytile + G;
        if (nt < NTILES) {
            __syncthreads();   // epilogue reads done before overwrite
            int nn0 = (nt % TILES_X) * BN;
            for (int c = tid; c < BN; c += NTHREADS) {
                reinterpret_cast<float*>(smem + SOFF_SC)[c] = wsc[nn0 + c];
                reinterpret_cast<float*>(smem + SOFF_BI)[c] = bias[nn0 + c];
            }
        }
    }
}

// ============================================================
// kernel_launch
// Inputs: x[8192*4096] f32, weight_int8[4096*4096] f32,
//         w_scale[4096] f32, bias[4096] f32, x_scale[1] f32
// Output: f32 [8192*4096]
// ============================================================
extern "C" void kernel_launch(void* const* d_in, const int* in_sizes, int n_in,
                              void* d_out, int out_size) {
    const float* x    = (const float*)d_in[0];
    const float* w    = (const float*)d_in[1];
    const float* wsc  = (const float*)d_in[2];
    const float* bias = (const float*)d_in[3];
    const float* xs   = (const float*)d_in[4];
    float* out = (float*)d_out;

    static int n_sm = 0;
    if (n_sm == 0) {
        cudaDeviceGetAttribute(&n_sm, cudaDevAttrMultiProcessorCount, 0);
        if (n_sm <= 0) n_sm = 148;
        cudaFuncSetAttribute(w8a8_gemm_kernel,
                             cudaFuncAttributeMaxDynamicSharedMemorySize,
                             SMEM_TOTAL);
    }

    // fused quantize pre-pass
    int n4x = MM * KK / 4;
    int n4w = NN * KK / 4;
    int n4tot = n4x + n4w;
    quantize_kernel<<<(n4tot + 255) / 256, 256>>>(
        (const float4*)x, (const float4*)w, xs, n4x, n4tot);

    // persistent GEMM
    int grid = n_sm < NTILES ? n_sm : NTILES;
    w8a8_gemm_kernel<<<grid, NTHREADS, SMEM_TOTAL>>>(out, wsc, bias, xs);
}

// round 10
// speedup vs baseline: 1.0469x; 1.0469x over previous
#include <cuda_runtime.h>
#include <cuda_bf16.h>
#include <cstdint>

// ============================================================
// W8A8 linear: out[M,N] = xs * (Xq[M,K] @ Wq[N,K]^T) * wsc[n] + bias[n]
//   M = 8192, N = 4096, K = 4096
// Base-sm_103 (compute_103 virtual arch; no tcgen05).
// Round 10: 2 CTAs per SM (BM=128 x BN=128 tiles, 4 warps each,
// launch_bounds(128,2)) so each SMSP holds warps from two
// INDEPENDENT CTAs -> kit barriers / epilogue / restage bubbles of
// one CTA are covered by the other. 3-stage BK=64 cp.async ring
// with wait_group(1) (unconditional per-kit commit keeps the
// group invariant in the tail). Persistent CTAs, continuous cursor.
// ============================================================

#define MM 8192
#define NN 4096
#define KK 4096

#define BM 128
#define BN 128
#define BK 64                 // bf16 elements; 128 bytes per row
#define STAGES 3
#define KITERS (KK / BK)      // 64
#define NTHREADS 128          // 4 warps
#define TILES_X (NN / BN)     // 32
#define NTILES ((MM / BM) * (NN / BN))   // 2048

// ---- device scratch: quantized bf16 operands ----
__device__ __align__(128) __nv_bfloat16 g_xq[(size_t)MM * KK];
__device__ __align__(128) __nv_bfloat16 g_wq[(size_t)NN * KK];

// ============================================================
// PTX helpers (base-arch only)
// ============================================================
__device__ __forceinline__ uint32_t smem_to_u32(const void* p) {
    uint32_t a;
    asm("{ .reg .u64 t; cvta.to.shared.u64 t, %1; cvt.u32.u64 %0, t; }"
        : "=r"(a) : "l"(p));
    return a;
}

__device__ __forceinline__ void cp_async16(uint32_t dst, const void* src) {
    asm volatile("cp.async.cg.shared.global [%0], [%1], 16;"
                 :: "r"(dst), "l"(src) : "memory");
}
#define CP_COMMIT() asm volatile("cp.async.commit_group;" ::: "memory")
#define CP_WAIT(n)  asm volatile("cp.async.wait_group %0;" :: "n"(n) : "memory")

#define LDMATRIX_X4(r, addr) \
    asm volatile("ldmatrix.sync.aligned.m8n8.x4.shared.b16 {%0,%1,%2,%3}, [%4];" \
                 : "=r"((r)[0]), "=r"((r)[1]), "=r"((r)[2]), "=r"((r)[3]) \
                 : "r"(addr))

// D(16x8 f32) += A(16x16 bf16, row-major) * B(16x8 bf16, col operand)
__device__ __forceinline__ void mma_bf16(float* d, const uint32_t* a,
                                         uint32_t b0, uint32_t b1) {
    asm volatile(
        "mma.sync.aligned.m16n8k16.row.col.f32.bf16.bf16.f32 "
        "{%0,%1,%2,%3}, {%4,%5,%6,%7}, {%8,%9}, {%0,%1,%2,%3};"
        : "+f"(d[0]), "+f"(d[1]), "+f"(d[2]), "+f"(d[3])
        : "r"(a[0]), "r"(a[1]), "r"(a[2]), "r"(a[3]),
          "r"(b0), "r"(b1));
}

// ============================================================
// Fused quantization pre-pass (x -> g_xq scaled; w -> g_wq passthrough)
// ============================================================
__device__ __forceinline__ uint2 quant4_bf16(float4 v, float inv) {
    float a = fminf(127.f, fmaxf(-128.f, rintf(v.x * inv)));
    float b = fminf(127.f, fmaxf(-128.f, rintf(v.y * inv)));
    float c = fminf(127.f, fmaxf(-128.f, rintf(v.z * inv)));
    float d = fminf(127.f, fmaxf(-128.f, rintf(v.w * inv)));
    __nv_bfloat162 lo = __floats2bfloat162_rn(a, b);
    __nv_bfloat162 hi = __floats2bfloat162_rn(c, d);
    uint2 p;
    p.x = *reinterpret_cast<uint32_t*>(&lo);
    p.y = *reinterpret_cast<uint32_t*>(&hi);
    return p;
}

__global__ void quantize_kernel(const float4* __restrict__ x4,
                                const float4* __restrict__ w4,
                                const float* __restrict__ xs_ptr,
                                int n4x, int n4tot) {
    int i = blockIdx.x * blockDim.x + threadIdx.x;
    if (i >= n4tot) return;
    if (i < n4x) {
        float inv = 1.0f / __ldg(xs_ptr);
        reinterpret_cast<uint2*>(g_xq)[i] = quant4_bf16(x4[i], inv);
    } else {
        int j = i - n4x;
        float4 v = w4[j];   // already integer-valued
        __nv_bfloat162 lo = __floats2bfloat162_rn(v.x, v.y);
        __nv_bfloat162 hi = __floats2bfloat162_rn(v.z, v.w);
        uint2 p;
        p.x = *reinterpret_cast<uint32_t*>(&lo);
        p.y = *reinterpret_cast<uint32_t*>(&hi);
        reinterpret_cast<uint2*>(g_wq)[j] = p;
    }
}

// ============================================================
// GEMM kernel: 2 CTAs/SM, persistent, 3-stage ring, BK=64.
//   128 threads = 4 warps, warp grid 2(m) x 2(n), warp tile 64x64.
//   Rows are 128B (= BK bf16); 16B-chunk XOR swizzle (validated
//   rounds 3-5): off = row*128 + ((c ^ (row&7)) << 4).
// Per kit: wait(1) -> barrier -> issue loads for kit+2 -> commit
// (unconditional) -> compute.
// ============================================================
#define SOFF_SC   0
#define SOFF_BI   512
#define SOFF_ST   1024
#define ROWB      128                          // bytes per smem row
#define STAGE_BYTES ((BM + BN) * ROWB)         // 32768
#define ASTAGE(s) (SOFF_ST + (s) * STAGE_BYTES)
#define BSTAGE(s) (ASTAGE(s) + BM * ROWB)
#define SMEM_TOTAL (SOFF_ST + STAGES * STAGE_BYTES)   // 99328

__device__ __forceinline__ uint32_t swz(int row, int chunk) {
    return (uint32_t)(row * ROWB + ((chunk ^ (row & 7)) << 4));
}

__device__ __forceinline__ void load_stage(uint32_t sb, int s, int kiter,
                                           int m0, int n0, int tid) {
    int k0 = kiter * BK;
    const __nv_bfloat16* Ab = g_xq + (size_t)m0 * KK + k0;
    const __nv_bfloat16* Bb = g_wq + (size_t)n0 * KK + k0;
    #pragma unroll
    for (int i = 0; i < (BM + BN) * 8 / NTHREADS; i++) {   // 16
        int idx = tid + i * NTHREADS;
        int row = idx >> 3;
        int c = idx & 7;                                   // 16B chunk (8 bf16)
        if (row < BM) {
            cp_async16(sb + ASTAGE(s) + swz(row, c),
                       Ab + (size_t)row * KK + c * 8);
        } else {
            int br = row - BM;
            cp_async16(sb + BSTAGE(s) + swz(br, c),
                       Bb + (size_t)br * KK + c * 8);
        }
    }
}

__global__ void __launch_bounds__(NTHREADS, 2)
w8a8_gemm_kernel(float* __restrict__ out,
                 const float* __restrict__ wsc,
                 const float* __restrict__ bias,
                 const float* __restrict__ xs_ptr) {
    extern __shared__ char smem[];
    uint32_t sb = smem_to_u32(smem);
    int tid  = threadIdx.x;
    int wid  = tid >> 5;
    int lane = tid & 31;
    int warp_m = wid & 1;     // m offset warp_m*64
    int warp_n = wid >> 1;    // n offset warp_n*64
    int G = gridDim.x;

    // ---- load cursor: continuous across this CTA's tile list ----
    int ltile = blockIdx.x;
    int lkit  = 0;
    int ls    = 0;

    // ---- stage sc/bias for first tile ----
    {
        int n0 = (blockIdx.x % TILES_X) * BN;
        for (int c = tid; c < BN; c += NTHREADS) {
            reinterpret_cast<float*>(smem + SOFF_SC)[c] = wsc[n0 + c];
            reinterpret_cast<float*>(smem + SOFF_BI)[c] = bias[n0 + c];
        }
    }

    // prologue: fill 2 of 3 stages
    #pragma unroll
    for (int p = 0; p < STAGES - 1; p++) {
        if (ltile < NTILES) {
            int lm0 = (ltile / TILES_X) * BM;
            int ln0 = (ltile % TILES_X) * BN;
            load_stage(sb, ls, lkit, lm0, ln0, tid);
            if (++ls == STAGES) ls = 0;
            if (++lkit == KITERS) { lkit = 0; ltile += G; }
        }
        CP_COMMIT();
    }

    float xs = __ldg(xs_ptr);

    // ldmatrix lane address components (validated rounds 3-9)
    int arow  = lane & 15;                        // A rows within m16
    int ahalf = lane >> 4;                        // A 16B half of k16 (32B)
    int brow  = (lane & 7) + ((lane & 16) >> 1);  // B n-rows (two n8 tiles)
    int bhalf = (lane >> 3) & 1;                  // B 16B half of k16

    int cs = 0;   // compute stage (FIFO with loads, carried across tiles)

    for (int mytile = blockIdx.x; mytile < NTILES; mytile += G) {
        int m0 = (mytile / TILES_X) * BM;
        int n0 = (mytile % TILES_X) * BN;

        float acc[4][8][4] = {};   // [m16 tile][n8 tile][frag]

        for (int kit = 0; kit < KITERS; kit++) {
            CP_WAIT(1);           // this kit's group done (one newer allowed)
            __syncthreads();      // visibility + stage-reuse safety

            // issue loads for kit+2 into ring stage ls
            if (ltile < NTILES) {
                int lm0 = (ltile / TILES_X) * BM;
                int ln0 = (ltile % TILES_X) * BN;
                load_stage(sb, ls, lkit, lm0, ln0, tid);
                if (++ls == STAGES) ls = 0;
                if (++lkit == KITERS) { lkit = 0; ltile += G; }
            }
            CP_COMMIT();          // unconditional: keeps wait(1) invariant

            uint32_t As = sb + ASTAGE(cs);
            uint32_t Bs = sb + BSTAGE(cs);
            if (++cs == STAGES) cs = 0;

            #pragma unroll
            for (int j = 0; j < BK / 16; j++) {      // 4 k16 steps
                uint32_t a[4][4];
                #pragma unroll
                for (int t = 0; t < 4; t++) {
                    int row = warp_m * 64 + t * 16 + arow;
                    LDMATRIX_X4(a[t], As + swz(row, j * 2 + ahalf));
                }
                uint32_t b[4][4];
                #pragma unroll
                for (int p = 0; p < 4; p++) {
                    int row = warp_n * 64 + p * 16 + brow;
                    LDMATRIX_X4(b[p], Bs + swz(row, j * 2 + bhalf));
                }
                #pragma unroll
                for (int t = 0; t < 4; t++) {
                    #pragma unroll
                    for (int p = 0; p < 4; p++) {
                        mma_bf16(acc[t][2 * p],     a[t], b[p][0], b[p][1]);
                        mma_bf16(acc[t][2 * p + 1], a[t], b[p][2], b[p][3]);
                    }
                }
            }
        }

        // -------- epilogue: out = acc * xs * sc[n] + bias[n] --------
        // (next tile's loads already in flight; co-resident CTA covers
        //  the tensor-pipe gap on this SM)
        const float* sc = reinterpret_cast<const float*>(smem + SOFF_SC);
        const float* bi = reinterpret_cast<const float*>(smem + SOFF_BI);
        int rbase = m0 + warp_m * 64 + (lane >> 2);
        #pragma unroll
        for (int t = 0; t < 4; t++) {
            #pragma unroll
            for (int q = 0; q < 8; q++) {
                int col = warp_n * 64 + q * 8 + (lane & 3) * 2;
                float s0 = xs * sc[col],     s1 = xs * sc[col + 1];
                float b0 = bi[col],          b1 = bi[col + 1];
                int row = rbase + t * 16;
                float2 v0, v1;
                v0.x = acc[t][q][0] * s0 + b0;
                v0.y = acc[t][q][1] * s1 + b1;
                v1.x = acc[t][q][2] * s0 + b0;
                v1.y = acc[t][q][3] * s1 + b1;
                *reinterpret_cast<float2*>(out + (size_t)row * NN + n0 + col) = v0;
                *reinterpret_cast<float2*>(out + (size_t)(row + 8) * NN + n0 + col) = v1;
            }
        }

        // restage sc/bias for next tile (separate smem region from stages)
        int nt = mytile + G;
        if (nt < NTILES) {
            __syncthreads();   // epilogue reads done before overwrite
            int nn0 = (nt % TILES_X) * BN;
            for (int c = tid; c < BN; c += NTHREADS) {
                reinterpret_cast<float*>(smem + SOFF_SC)[c] = wsc[nn0 + c];
                reinterpret_cast<float*>(smem + SOFF_BI)[c] = bias[nn0 + c];
            }
        }
    }
}

// ============================================================
// kernel_launch
// Inputs: x[8192*4096] f32, weight_int8[4096*4096] f32,
//         w_scale[4096] f32, bias[4096] f32, x_scale[1] f32
// Output: f32 [8192*4096]
// ============================================================
extern "C" void kernel_launch(void* const* d_in, const int* in_sizes, int n_in,
                              void* d_out, int out_size) {
    const float* x    = (const float*)d_in[0];
    const float* w    = (const float*)d_in[1];
    const float* wsc  = (const float*)d_in[2];
    const float* bias = (const float*)d_in[3];
    const float* xs   = (const float*)d_in[4];
    float* out = (float*)d_out;

    static int n_sm = 0;
    if (n_sm == 0) {
        cudaDeviceGetAttribute(&n_sm, cudaDevAttrMultiProcessorCount, 0);
        if (n_sm <= 0) n_sm = 148;
        cudaFuncSetAttribute(w8a8_gemm_kernel,
                             cudaFuncAttributeMaxDynamicSharedMemorySize,
                             SMEM_TOTAL);
    }

    // fused quantize pre-pass
    int n4x = MM * KK / 4;
    int n4w = NN * KK / 4;
    int n4tot = n4x + n4w;
    quantize_kernel<<<(n4tot + 255) / 256, 256>>>(
        (const float4*)x, (const float4*)w, xs, n4x, n4tot);

    // persistent GEMM, 2 CTAs per SM
    int grid = 2 * n_sm;
    if (grid > NTILES) grid = NTILES;
    w8a8_gemm_kernel<<<grid, NTHREADS, SMEM_TOTAL>>>(out, wsc, bias, xs);
}